// round 13
// baseline (speedup 1.0000x reference)
#include <cuda_runtime.h>
#include <math.h>

// 2-layer LSTM H=512 B=16 T=6574. Persistent kernel, 128 CTAs x 256 thr.
// CTA owns h-indices [4c,4c+4) = 16 gate rows/layer. Weights register-resident.
// Pipelined: interval k computes h1(k) AND h2(k-1); ONE grid barrier/step.
// h state double-buffered by parity. Barrier: 2-level arrival tree with
// scoped acq_rel atomics (no CCTL L1 flush). GEMV smem reads are 16B-
// interleaved across half-warps -> bank-conflict-free broadcast LDS.128.

#define NCTA 128
#define NTHR 256
#define HD   512
#define BQ   16
#define PSTR 288      // floats per partial slot (16 rows * 18)
#define RSTR 18

typedef unsigned long long u64;

__device__ __align__(16) float g_h1[2][BQ * HD];
__device__ __align__(16) float g_h2[2][BQ * HD];
__device__ __align__(16) unsigned g_cnt[8];   // group counters (16 CTAs each)
__device__ unsigned g_root = 0;
__device__ unsigned g_gen  = 0;

__device__ __forceinline__ void ffma2(u64& d, u64 a, u64 b) {
    asm("fma.rn.f32x2 %0, %1, %2, %0;" : "+l"(d) : "l"(a), "l"(b));
}
__device__ __forceinline__ float f2sum(u64 a) {
    float lo, hi;
    asm("mov.b64 {%0,%1}, %2;" : "=f"(lo), "=f"(hi) : "l"(a));
    return lo + hi;
}
__device__ __forceinline__ float sigmoidf_(float x) { return 1.0f / (1.0f + expf(-x)); }

__device__ __forceinline__ float4 ldcg_f4(const float4* p) {
    float4 v;
    asm volatile("ld.global.cg.v4.f32 {%0,%1,%2,%3}, [%4];"
                 : "=f"(v.x), "=f"(v.y), "=f"(v.z), "=f"(v.w) : "l"(p) : "memory");
    return v;
}
__device__ __forceinline__ unsigned atom_add_acqrel(unsigned* p, unsigned v) {
    unsigned old;
    asm volatile("atom.acq_rel.gpu.global.add.u32 %0, [%1], %2;"
                 : "=r"(old) : "l"(p), "r"(v) : "memory");
    return old;
}
__device__ __forceinline__ void st_relaxed_u32(unsigned* p, unsigned v) {
    asm volatile("st.relaxed.gpu.global.u32 [%0], %1;" :: "l"(p), "r"(v) : "memory");
}
__device__ __forceinline__ void st_release_u32(unsigned* p, unsigned v) {
    asm volatile("st.release.gpu.global.u32 [%0], %1;" :: "l"(p), "r"(v) : "memory");
}
__device__ __forceinline__ unsigned ld_acquire_u32(const unsigned* p) {
    unsigned v;
    asm volatile("ld.acquire.gpu.global.u32 %0, [%1];" : "=r"(v) : "l"(p) : "memory");
    return v;
}
__device__ __forceinline__ unsigned ld_relaxed_u32(const unsigned* p) {
    unsigned v;
    asm volatile("ld.relaxed.gpu.global.u32 %0, [%1];" : "=r"(v) : "l"(p) : "memory");
    return v;
}

// Grid barrier: 2-level arrival tree, replay-safe "wait-for-change" protocol.
// bar.sync (cta scope) + tid0's acq_rel.gpu atomics form the cross-CTA
// release/acquire chain; no gpu-scope fence (no L1D flush) needed since all
// cross-CTA data reads use ld.cg (L2-direct).
__device__ __forceinline__ void grid_barrier(int cta) {
    __syncthreads();
    if (threadIdx.x == 0) {
        unsigned gen = ld_relaxed_u32(&g_gen);
        if (atom_add_acqrel(&g_cnt[cta & 7], 1u) == 15u) {
            st_relaxed_u32(&g_cnt[cta & 7], 0u);       // ordered before root arrival (release)
            if (atom_add_acqrel(&g_root, 1u) == 7u) {
                st_relaxed_u32(&g_root, 0u);           // ordered before gen flip (release)
                st_release_u32(&g_gen, gen + 1u);
            }
        }
        while (ld_acquire_u32(&g_gen) == gen) { }
    }
    __syncthreads();
}

// GEMV partial: lane owns one row; weights cover floats
// [base + i*8 + s*4, +4) for i in 0..NI. The two half-warps (s=0/1) read
// 16B-adjacent addresses -> conflict-free broadcast LDS.128.
template <int NI>
__device__ __forceinline__ void gemv_part(const u64* __restrict__ w,
                                          const float* __restrict__ HB,
                                          int koff, float* __restrict__ pdst) {
    for (int b2 = 0; b2 < 8; ++b2) {
        const ulonglong2* h0 = (const ulonglong2*)(HB + (2 * b2) * HD + koff);
        const ulonglong2* h1 = (const ulonglong2*)(HB + (2 * b2 + 1) * HD + koff);
        u64 a0 = 0, a1 = 0;
#pragma unroll
        for (int i = 0; i < NI; ++i) {
            ulonglong2 v0 = h0[2 * i];      // 16B at float offset koff + i*8
            ulonglong2 v1 = h1[2 * i];
            ffma2(a0, w[2 * i], v0.x); ffma2(a0, w[2 * i + 1], v0.y);
            ffma2(a1, w[2 * i], v1.x); ffma2(a1, w[2 * i + 1], v1.y);
        }
        float r0 = f2sum(a0), r1 = f2sum(a1);
        u64 pk;
        asm("mov.b64 %0, {%1,%2};" : "=l"(pk) : "f"(r0), "f"(r1));
        *(u64*)(pdst + 2 * b2) = pk;
    }
}

__global__ void __launch_bounds__(NTHR, 1) lstm_kernel(
    const float* __restrict__ input,
    const float* __restrict__ Wih1, const float* __restrict__ Whh1,
    const float* __restrict__ bih1, const float* __restrict__ bhh1,
    const float* __restrict__ Wih2, const float* __restrict__ Whh2,
    const float* __restrict__ bih2, const float* __restrict__ bhh2,
    const float* __restrict__ Wout, const float* __restrict__ bout,
    float* __restrict__ out, int T)
{
    extern __shared__ float sm[];
    float* HB1   = sm;                  // [16][512] h1(k-1)
    float* HB2   = HB1 + BQ * HD;       // [16][512] h2(k-2)
    float* PART1 = HB2 + BQ * HD;       // [8][288]   layer-1 partials
    float* PART2 = PART1 + 8 * PSTR;    // [24][288]  layer-2 partials
    float* GVAL1 = PART2 + 24 * PSTR;   // [256]
    float* GVAL2 = GVAL1 + 256;         // [256]
    float* BIAS1 = GVAL2 + 256;         // [16]
    float* BIAS2 = BIAS1 + 16;          // [16]
    float* WI1s  = BIAS2 + 16;          // [16][2]
    float* XS    = WI1s + 32;           // [2][16]
    float* C1S   = XS + 32;             // [64]
    float* C2S   = C1S + 64;            // [64]
    float* WoutS = C2S + 64;            // [512]

    const int tid  = threadIdx.x;
    const int cta  = blockIdx.x;
    const int warp = tid >> 5, lane = tid & 31;
    const int r    = lane & 15, s = lane >> 4;
    const int hbase = cta * 4;
    const int jrow = (r >> 2) * HD + hbase + (r & 3);

    // ---- weight preload into registers (16B-interleaved k-mapping) ----
    const float* WAsrc = (warp < 4) ? Whh1 : Whh2;
    const int koffA = (warp & 3) * 128 + s * 4;
    u64 wA[32];
    {
        const u64* gp = (const u64*)(WAsrc + (size_t)jrow * HD + koffA);
#pragma unroll
        for (int i = 0; i < 16; ++i) { wA[2 * i] = gp[4 * i]; wA[2 * i + 1] = gp[4 * i + 1]; }
    }
    const int koffB = warp * 64 + s * 4;
    u64 wB[16];
    {
        const u64* gp = (const u64*)(Wih2 + (size_t)jrow * HD + koffB);
#pragma unroll
        for (int i = 0; i < 8; ++i) { wB[2 * i] = gp[4 * i]; wB[2 * i + 1] = gp[4 * i + 1]; }
    }

    // ---- misc preamble ----
    if (tid < 16) {
        int jt = (tid >> 2) * HD + hbase + (tid & 3);
        BIAS1[tid] = bih1[jt] + bhh1[jt];
        BIAS2[tid] = bih2[jt] + bhh2[jt];
        WI1s[2 * tid]     = Wih1[2 * jt];
        WI1s[2 * tid + 1] = Wih1[2 * jt + 1];
    }
    for (int i = tid; i < BQ * HD; i += NTHR) { HB1[i] = 0.0f; HB2[i] = 0.0f; }
    for (int i = tid; i < HD; i += NTHR) WoutS[i] = Wout[i];
    if (tid < 64) { C1S[tid] = 0.0f; C2S[tid] = 0.0f; }
    const float bo = bout[0];
    __syncthreads();

    float* pdstA = ((warp < 4) ? PART1 : PART2) + ((warp & 3) * 2 + s) * PSTR + r * RSTR;
    float* pdstB = PART2 + (8 + warp * 2 + s) * PSTR + r * RSTR;
    const float* HBA = (warp < 4) ? HB1 : HB2;

    // Pipelined intervals: k = 0..T. Interval k computes h1(k) (k<T) and
    // h2(k-1) (k>=1; k==0 publishes zeros), writes to parity buffer k&1,
    // ONE barrier, reloads HB1/HB2 from buffer k&1, emits out(k-1).
    for (int k = 0; k <= T; ++k) {
        const bool do_l1 = (k < T);
        const bool do_l2 = (k >= 1);
        const int  wr    = k & 1;

        // stage x(k) while GEMVs run (read after the next __syncthreads)
        if (do_l1 && tid < 32) {
            int b = tid & 15, c = tid >> 4;
            XS[c * 16 + b] = input[((size_t)b * T + k) * 2 + c];
        }

        // fused GEMV phase
        gemv_part<16>(wA, HBA, koffA, pdstA);   // w0-3: Whh1@h1(k-1); w4-7: Whh2@h2(k-2)
        gemv_part<8>(wB, HB1, koffB, pdstB);    // all: Wih2@h1(k-1)
        __syncthreads();

        // reductions for both layers (256 (row,b) pairs each)
        {
            int rr = tid >> 4, b = tid & 15;
            float s1 = BIAS1[rr] + WI1s[2 * rr] * XS[b] + WI1s[2 * rr + 1] * XS[16 + b];
#pragma unroll
            for (int p = 0; p < 8; ++p) s1 += PART1[p * PSTR + rr * RSTR + b];
            GVAL1[rr * 16 + b] = s1;
            float s2 = BIAS2[rr];
#pragma unroll
            for (int p = 0; p < 24; ++p) s2 += PART2[p * PSTR + rr * RSTR + b];
            GVAL2[rr * 16 + b] = s2;
        }
        __syncthreads();

        // both cell updates concurrently, publish into parity buffer wr
        if (tid < 64) {
            if (do_l1) {
                int l = tid >> 4, b = tid & 15;
                float gi = GVAL1[(l) * 16 + b];
                float gf = GVAL1[(4 + l) * 16 + b];
                float gc = GVAL1[(8 + l) * 16 + b];
                float go = GVAL1[(12 + l) * 16 + b];
                float iv = sigmoidf_(gi), fv = sigmoidf_(gf);
                float cv = tanhf(gc), ov = sigmoidf_(go);
                float c = fv * C1S[tid] + iv * cv;
                C1S[tid] = c;
                g_h1[wr][b * HD + hbase + l] = ov * tanhf(c);
            }
        } else if (tid < 128) {
            int u = tid - 64;
            int l = u >> 4, b = u & 15;
            if (do_l2) {
                float gi = GVAL2[(l) * 16 + b];
                float gf = GVAL2[(4 + l) * 16 + b];
                float gc = GVAL2[(8 + l) * 16 + b];
                float go = GVAL2[(12 + l) * 16 + b];
                float iv = sigmoidf_(gi), fv = sigmoidf_(gf);
                float cv = tanhf(gc), ov = sigmoidf_(go);
                float c = fv * C2S[u] + iv * cv;
                C2S[u] = c;
                g_h2[wr][b * HD + hbase + l] = ov * tanhf(c);
            } else {
                // k == 0: publish h2(-1) = 0 so replays are deterministic
                g_h2[wr][b * HD + hbase + l] = 0.0f;
            }
        }
        grid_barrier(cta);

        // reload h1(k), h2(k-1) from parity buffer wr: 2*2048 float4
        {
            const float4* s1 = (const float4*)g_h1[wr];
            const float4* s2 = (const float4*)g_h2[wr];
            float4* d1 = (float4*)HB1;
            float4* d2 = (float4*)HB2;
#pragma unroll
            for (int i = 0; i < 8; ++i) d1[tid + i * NTHR] = ldcg_f4(s1 + tid + i * NTHR);
#pragma unroll
            for (int i = 0; i < 8; ++i) d2[tid + i * NTHR] = ldcg_f4(s2 + tid + i * NTHR);
        }
        __syncthreads();

        // output head: HB2 now holds h2(k-1); CTA b<16 emits out[b][k-1]
        if (do_l2 && cta < BQ && warp == 0) {
            float ssum = 0.0f;
            const float* h2p = HB2 + cta * HD;
#pragma unroll
            for (int q = 0; q < 16; ++q)
                ssum += h2p[lane + q * 32] * WoutS[lane + q * 32];
#pragma unroll
            for (int o = 16; o; o >>= 1) ssum += __shfl_xor_sync(0xffffffffu, ssum, o);
            if (lane == 0) out[(size_t)cta * T + (k - 1)] = ssum + bo;
        }
    }
}

extern "C" void kernel_launch(void* const* d_in, const int* in_sizes, int n_in,
                              void* d_out, int out_size)
{
    const float* input = (const float*)d_in[0];
    const float* Wih1  = (const float*)d_in[1];
    const float* Whh1  = (const float*)d_in[2];
    const float* bih1  = (const float*)d_in[3];
    const float* bhh1  = (const float*)d_in[4];
    const float* Wih2  = (const float*)d_in[5];
    const float* Whh2  = (const float*)d_in[6];
    const float* bih2  = (const float*)d_in[7];
    const float* bhh2  = (const float*)d_in[8];
    const float* Wout  = (const float*)d_in[9];
    const float* bout  = (const float*)d_in[10];

    int T = in_sizes[0] / (BQ * 2);

    size_t smem_floats = 2 * BQ * HD          // HB1, HB2
                       + 8 * PSTR + 24 * PSTR // PART1, PART2
                       + 256 + 256            // GVAL1, GVAL2
                       + 16 + 16 + 32 + 32    // BIAS1, BIAS2, WI1, XS
                       + 64 + 64 + HD;        // C1S, C2S, WoutS
    size_t smem_bytes = smem_floats * sizeof(float);

    cudaFuncSetAttribute(lstm_kernel, cudaFuncAttributeMaxDynamicSharedMemorySize,
                         (int)smem_bytes);

    lstm_kernel<<<NCTA, NTHR, smem_bytes>>>(
        input, Wih1, Whh1, bih1, bhh1, Wih2, Whh2, bih2, bhh2, Wout, bout,
        (float*)d_out, T);
}